// round 7
// baseline (speedup 1.0000x reference)
#include <cuda_runtime.h>
#include <cstdint>

#define E_DIM 2048
#define H_NUM 32
#define HD 64
#define P_LEN 4096
#define S_LEN 4100
#define M_ROWS 64
#define CH 128
#define NCH 32
#define NEG_MAX (-3.4028234663852886e38f)

// ---------------- scratch (device globals: no allocs allowed) ----------------
__device__ __align__(256) float g_q[M_ROWS * E_DIM];      // holds tf32-rounded, pre-scaled Q
__device__ __align__(256) float g_k[M_ROWS * E_DIM];
__device__ __align__(256) float g_v[M_ROWS * E_DIM];
__device__ __align__(256) float g_attn[M_ROWS * E_DIM];
// opart layout: [m][part][g], part = h*4 + quarter  (m*8192 + part*64 + g)
__device__ __align__(256) float g_opart[M_ROWS * H_NUM * 4 * HD];
// pm/pl layout: [m][part]  (m*128 + part)
__device__ __align__(256) float g_pm[M_ROWS * H_NUM * 4];
__device__ __align__(256) float g_pl[M_ROWS * H_NUM * 4];
__device__ __align__(256) float g_pp[12 * M_ROWS * E_DIM];   // split-K partials

// ---------------- helpers ----------------
__device__ __forceinline__ uint32_t f2tf(float f) {
    uint32_t u;
    asm("cvt.rna.tf32.f32 %0, %1;" : "=r"(u) : "f"(f));
    return u;
}

__device__ __forceinline__ void mma_tf32(float* c, const uint32_t* a, uint32_t b0, uint32_t b1) {
    asm volatile(
        "mma.sync.aligned.m16n8k8.row.col.f32.tf32.tf32.f32 "
        "{%0,%1,%2,%3},{%4,%5,%6,%7},{%8,%9},{%0,%1,%2,%3};"
        : "+f"(c[0]), "+f"(c[1]), "+f"(c[2]), "+f"(c[3])
        : "r"(a[0]), "r"(a[1]), "r"(a[2]), "r"(a[3]), "r"(b0), "r"(b1));
}

__device__ __forceinline__ void cp16(float* smem_dst, const float* gsrc) {
    uint32_t s = (uint32_t)__cvta_generic_to_shared(smem_dst);
    asm volatile("cp.async.cg.shared.global [%0], [%1], 16;" :: "r"(s), "l"(gsrc));
}
__device__ __forceinline__ void cp_commit() {
    asm volatile("cp.async.commit_group;");
}
template<int N> __device__ __forceinline__ void cp_wait() {
    asm volatile("cp.async.wait_group %0;" :: "n"(N));
}

// ---------------- W-major split-K projection GEMM ----------------
// C[f, t] = sum_k W[f,k] * A[t,k]; grid (32, n_mats, ksplit); A==nullptr -> g_attn.
__global__ void __launch_bounds__(256) gemm_w(
    const float* __restrict__ A,
    const float* __restrict__ W0, const float* __restrict__ W1, const float* __restrict__ W2,
    int kspan)
{
    extern __shared__ float sm[];
    const int STAGE = 128 * 36;

    if (A == nullptr) A = g_attn;
    const float* W = (blockIdx.y == 0) ? W0 : (blockIdx.y == 1) ? W1 : W2;
    const int fbase = blockIdx.x * 64;
    const int k0 = blockIdx.z * kspan;
    float* part = g_pp + (size_t)(blockIdx.z * gridDim.y + blockIdx.y) * (M_ROWS * E_DIM);

    const int tid = threadIdx.x;
    const int lane = tid & 31, wid = tid >> 5;
    const int rb = lane >> 2, cq = lane & 3;
    const int m0 = (wid >> 1) * 16;
    const int n0 = (wid & 1) * 32;

    float c[4][4];
#pragma unroll
    for (int i = 0; i < 4; i++)
#pragma unroll
        for (int j = 0; j < 4; j++) c[i][j] = 0.0f;

    auto load_stage = [&](int buf, int kk0) {
        float* ws = sm + buf * STAGE;
        float* as = ws + 64 * 36;
        int row = tid >> 3, kc = tid & 7;
        cp16(ws + row * 36 + kc * 4,        W + (size_t)(fbase + row) * E_DIM + kk0 + kc * 4);
        cp16(ws + (row + 32) * 36 + kc * 4, W + (size_t)(fbase + row + 32) * E_DIM + kk0 + kc * 4);
        cp16(as + row * 36 + kc * 4,        A + (row) * E_DIM + kk0 + kc * 4);
        cp16(as + (row + 32) * 36 + kc * 4, A + (row + 32) * E_DIM + kk0 + kc * 4);
    };

#pragma unroll
    for (int s = 0; s < 3; s++) { load_stage(s, k0 + s * 32); cp_commit(); }

    const int NITER = kspan / 32;
    for (int it = 0; it < NITER; it++) {
        cp_wait<2>();
        __syncthreads();
        float* ws = sm + (it & 3) * STAGE;
        float* as = ws + 64 * 36;
#pragma unroll
        for (int ks = 0; ks < 4; ks++) {
            int kk = ks * 8 + cq;
            uint32_t a[4];
            a[0] = f2tf(ws[(m0 + rb) * 36 + kk]);
            a[1] = f2tf(ws[(m0 + 8 + rb) * 36 + kk]);
            a[2] = f2tf(ws[(m0 + rb) * 36 + kk + 4]);
            a[3] = f2tf(ws[(m0 + 8 + rb) * 36 + kk + 4]);
#pragma unroll
            for (int nf = 0; nf < 4; nf++) {
                int nn = n0 + nf * 8 + rb;
                uint32_t b0 = f2tf(as[nn * 36 + kk]);
                uint32_t b1 = f2tf(as[nn * 36 + kk + 4]);
                mma_tf32(c[nf], a, b0, b1);
            }
        }
        int nx = it + 3;
        if (nx < NITER) load_stage(nx & 3, k0 + nx * 32);
        cp_commit();
    }

    const int f = fbase + m0 + rb;
#pragma unroll
    for (int nf = 0; nf < 4; nf++) {
        int t0 = n0 + nf * 8 + cq * 2;
        part[t0 * E_DIM + f]           = c[nf][0];
        part[(t0 + 1) * E_DIM + f]     = c[nf][1];
        part[t0 * E_DIM + f + 8]       = c[nf][2];
        part[(t0 + 1) * E_DIM + f + 8] = c[nf][3];
    }
}

// ---------------- reduce split-K partials ----------------
// QKV: slots {mat, mat+3, mat+6, mat+9}; Q gets scale 0.125 AND tf32 pre-rounding.
__global__ void __launch_bounds__(256) reduce_qkv(
    const float* __restrict__ bq, const float* __restrict__ bk, const float* __restrict__ bv)
{
    int gid = blockIdx.x * 256 + threadIdx.x;    // 0..98303
    int mat = gid >> 15;
    int r = gid & 32767;
    int f4 = r & 511;
    const float4* pp = (const float4*)g_pp;
    float4 a = pp[(size_t)mat * 32768 + r];
    float4 b = pp[(size_t)(mat + 3) * 32768 + r];
    float4 c = pp[(size_t)(mat + 6) * 32768 + r];
    float4 d = pp[(size_t)(mat + 9) * 32768 + r];
    const float* bias = (mat == 0) ? bq : (mat == 1) ? bk : bv;
    float4 bb = ((const float4*)bias)[f4];
    float4 o;
    o.x = a.x + b.x + c.x + d.x + bb.x;
    o.y = a.y + b.y + c.y + d.y + bb.y;
    o.z = a.z + b.z + c.z + d.z + bb.z;
    o.w = a.w + b.w + c.w + d.w + bb.w;
    if (mat == 0) {
        o.x = __uint_as_float(f2tf(o.x * 0.125f));
        o.y = __uint_as_float(f2tf(o.y * 0.125f));
        o.z = __uint_as_float(f2tf(o.z * 0.125f));
        o.w = __uint_as_float(f2tf(o.w * 0.125f));
    }
    float* out = (mat == 0) ? g_q : (mat == 1) ? g_k : g_v;
    ((float4*)out)[r] = o;
}

// O-proj: slots 0..7, add bias, write d_out. grid 128x256
__global__ void __launch_bounds__(256) reduce_o(const float* __restrict__ bo, float* __restrict__ out)
{
    int r = blockIdx.x * 256 + threadIdx.x;      // 0..32767
    int f4 = r & 511;
    const float4* pp = (const float4*)g_pp;
    float4 bb = ((const float4*)bo)[f4];
    float ox = bb.x, oy = bb.y, oz = bb.z, ow = bb.w;
#pragma unroll
    for (int s = 0; s < 8; s++) {
        float4 a = pp[(size_t)s * 32768 + r];
        ox += a.x; oy += a.y; oz += a.z; ow += a.w;
    }
    ((float4*)out)[r] = make_float4(ox, oy, oz, ow);
}

// ---------------- attention: online-softmax flash decoding ----------------
// 128 blocks = (head h = bid>>2, quarter = bid&3). Each block: 8 chunks of 128 positions,
// Q loaded once, KV double-buffered, running (M, L, rescale f) per row, O accum in regs.
__global__ void __launch_bounds__(256, 1) attn_part(
    const float* __restrict__ kpast, const float* __restrict__ vpast,
    const float* __restrict__ mask)
{
    extern __shared__ float sm[];
    float* qs = sm;                     // [64][68]  (tf32 bits)
    float* ks = qs + 64 * 68;           // 2 x [128][68]
    float* vs = ks + 2 * 128 * 68;      // 2 x [128][72]
    float* ss = vs + 2 * 128 * 72;      // [64][132]
    float* rowM = ss + 64 * 132;        // [64]
    float* rowL = rowM + 64;            // [64]
    float* rowF = rowL + 64;            // [64]
    uint32_t* ssb = (uint32_t*)ss;

    const int tid = threadIdx.x;
    const int lane = tid & 31, wid = tid >> 5;
    const int rb = lane >> 2, cq = lane & 3;
    const int n0 = wid * 16;
    const int d0 = wid * 8;

    const int h = blockIdx.x >> 2;
    const int quarter = blockIdx.x & 3;
    const int c_base = quarter * 8;
    const int pidx = h * 4 + quarter;

    auto prefetch_kv = [&](int c, int slot) {
        int s0 = c * CH;
        float* kb = ks + slot * (128 * 68);
        float* vb = vs + slot * (128 * 72);
#pragma unroll
        for (int i = 0; i < 8; i++) {
            int cc = tid + i * 256;
            int s = cc >> 4, kc = cc & 15;
            cp16(kb + s * 68 + kc * 4, kpast + ((size_t)h * P_LEN + s0 + s) * HD + kc * 4);
        }
#pragma unroll
        for (int i = 0; i < 8; i++) {
            int cc = tid + i * 256;
            int s = cc >> 4, kc = cc & 15;
            cp16(vb + s * 72 + kc * 4, vpast + ((size_t)h * P_LEN + s0 + s) * HD + kc * 4);
        }
        cp_commit();
    };

    // group 0: Q (once per block) + first KV chunk
#pragma unroll
    for (int i = 0; i < 4; i++) {
        int cc = tid + i * 256;
        int m = cc >> 4, kc = cc & 15;
        cp16(qs + m * 68 + kc * 4, g_q + m * E_DIM + h * HD + kc * 4);
    }
    {
        int s0 = c_base * CH;
#pragma unroll
        for (int i = 0; i < 8; i++) {
            int cc = tid + i * 256;
            int s = cc >> 4, kc = cc & 15;
            cp16(ks + s * 68 + kc * 4, kpast + ((size_t)h * P_LEN + s0 + s) * HD + kc * 4);
        }
#pragma unroll
        for (int i = 0; i < 8; i++) {
            int cc = tid + i * 256;
            int s = cc >> 4, kc = cc & 15;
            cp16(vs + s * 72 + kc * 4, vpast + ((size_t)h * P_LEN + s0 + s) * HD + kc * 4);
        }
        cp_commit();
    }

    // init running stats (warp-owned rows) and O accumulators
#pragma unroll
    for (int rr = 0; rr < 8; rr++) {
        int r = wid * 8 + rr;
        if (lane == 0) { rowM[r] = NEG_MAX; rowL[r] = 0.0f; }
    }
    float o[4][4];
#pragma unroll
    for (int i = 0; i < 4; i++)
#pragma unroll
        for (int j = 0; j < 4; j++) o[i][j] = 0.0f;

    for (int ci = 0; ci < 8; ci++) {
        const int c = c_base + ci;
        const int s0 = c * CH;
        const int slot = ci & 1;
        float* kb = ks + slot * (128 * 68);
        float* vb = vs + slot * (128 * 72);

        // mask values for this chunk (registers; overlaps pending cp.async)
        float2 mk0[4][2], mk1[4][2];
#pragma unroll
        for (int mf = 0; mf < 4; mf++) {
            int r0 = mf * 16 + rb, r1 = r0 + 8;
#pragma unroll
            for (int nf = 0; nf < 2; nf++) {
                int sg = s0 + n0 + nf * 8 + cq * 2;
                mk0[mf][nf] = *(const float2*)(mask + r0 * S_LEN + sg);
                mk1[mf][nf] = *(const float2*)(mask + r1 * S_LEN + sg);
            }
        }

        if (ci + 1 < 8) { prefetch_kv(c + 1, (ci + 1) & 1); cp_wait<1>(); }
        else            { cp_wait<0>(); }
        __syncthreads();

        // GEMM-S: scores[64 x 128] = Q @ Kchunk^T
        float cacc[4][2][4];
#pragma unroll
        for (int i = 0; i < 4; i++)
#pragma unroll
            for (int j = 0; j < 2; j++)
#pragma unroll
                for (int k = 0; k < 4; k++) cacc[i][j][k] = 0.0f;

#pragma unroll
        for (int kst = 0; kst < 8; kst++) {
            int kk = kst * 8 + cq;
            uint32_t a[4][4], b[2][2];
#pragma unroll
            for (int mf = 0; mf < 4; mf++) {
                int r = mf * 16 + rb;
                a[mf][0] = __float_as_uint(qs[r * 68 + kk]);        // pre-rounded tf32
                a[mf][1] = __float_as_uint(qs[(r + 8) * 68 + kk]);
                a[mf][2] = __float_as_uint(qs[r * 68 + kk + 4]);
                a[mf][3] = __float_as_uint(qs[(r + 8) * 68 + kk + 4]);
            }
#pragma unroll
            for (int nf = 0; nf < 2; nf++) {
                int sc = n0 + nf * 8 + rb;
                b[nf][0] = f2tf(kb[sc * 68 + kk]);
                b[nf][1] = f2tf(kb[sc * 68 + kk + 4]);
            }
#pragma unroll
            for (int mf = 0; mf < 4; mf++)
#pragma unroll
                for (int nf = 0; nf < 2; nf++)
                    mma_tf32(cacc[mf][nf], a[mf], b[nf][0], b[nf][1]);
        }

        // scores -> ss with mask add + clamp
#pragma unroll
        for (int mf = 0; mf < 4; mf++) {
            int r0 = mf * 16 + rb, r1 = r0 + 8;
#pragma unroll
            for (int nf = 0; nf < 2; nf++) {
                int col = n0 + nf * 8 + cq * 2;
                ss[r0 * 132 + col]     = fmaxf(cacc[mf][nf][0] + mk0[mf][nf].x, NEG_MAX);
                ss[r0 * 132 + col + 1] = fmaxf(cacc[mf][nf][1] + mk0[mf][nf].y, NEG_MAX);
                ss[r1 * 132 + col]     = fmaxf(cacc[mf][nf][2] + mk1[mf][nf].x, NEG_MAX);
                ss[r1 * 132 + col + 1] = fmaxf(cacc[mf][nf][3] + mk1[mf][nf].y, NEG_MAX);
            }
        }
        __syncthreads();

        // online softmax: warp owns 8 rows; update running M/L, emit rescale factor f
#pragma unroll
        for (int rr = 0; rr < 8; rr++) {
            int r = wid * 8 + rr;
            int base = r * 132 + lane * 4;
            float v0 = ss[base], v1 = ss[base + 1], v2 = ss[base + 2], v3 = ss[base + 3];
            float mx = fmaxf(fmaxf(v0, v1), fmaxf(v2, v3));
#pragma unroll
            for (int off = 16; off > 0; off >>= 1)
                mx = fmaxf(mx, __shfl_xor_sync(0xffffffffu, mx, off));
            float Mold = rowM[r];
            float Mnew = fmaxf(Mold, mx);
            float p0 = __expf(v0 - Mnew), p1 = __expf(v1 - Mnew);
            float p2 = __expf(v2 - Mnew), p3 = __expf(v3 - Mnew);
            float sum = (p0 + p1) + (p2 + p3);
#pragma unroll
            for (int off = 16; off > 0; off >>= 1)
                sum += __shfl_xor_sync(0xffffffffu, sum, off);
            ssb[base] = f2tf(p0); ssb[base + 1] = f2tf(p1);
            ssb[base + 2] = f2tf(p2); ssb[base + 3] = f2tf(p3);
            if (lane == 0) {
                float f = __expf(Mold - Mnew);
                rowM[r] = Mnew;
                rowL[r] = rowL[r] * f + sum;
                rowF[r] = f;
            }
        }
        __syncthreads();

        // GEMM-O: o = o * f(row) + probs @ V
#pragma unroll
        for (int mf = 0; mf < 4; mf++) {
            int r0 = mf * 16 + rb;
            float f0 = rowF[r0], f1 = rowF[r0 + 8];
            o[mf][0] *= f0; o[mf][1] *= f0;
            o[mf][2] *= f1; o[mf][3] *= f1;
        }
#pragma unroll
        for (int kst = 0; kst < 16; kst++) {
            int kk = kst * 8 + cq;
            uint32_t a[4][4];
#pragma unroll
            for (int mf = 0; mf < 4; mf++) {
                int r = mf * 16 + rb;
                a[mf][0] = ssb[r * 132 + kk];
                a[mf][1] = ssb[(r + 8) * 132 + kk];
                a[mf][2] = ssb[r * 132 + kk + 4];
                a[mf][3] = ssb[(r + 8) * 132 + kk + 4];
            }
            uint32_t b0 = f2tf(vb[kk * 72 + d0 + rb]);
            uint32_t b1 = f2tf(vb[(kk + 4) * 72 + d0 + rb]);
#pragma unroll
            for (int mf = 0; mf < 4; mf++)
                mma_tf32(o[mf], a[mf], b0, b1);
        }
        __syncthreads();   // ssb/rowF reads done before next chunk overwrites
    }

    // final stores: O partial + (M, L) per row for this (h, quarter)
#pragma unroll
    for (int rr = 0; rr < 8; rr++) {
        int r = wid * 8 + rr;
        if (lane == 0) {
            g_pm[r * 128 + pidx] = rowM[r];
            g_pl[r * 128 + pidx] = rowL[r];
        }
    }
#pragma unroll
    for (int mf = 0; mf < 4; mf++) {
        int r0 = mf * 16 + rb;
        int cd = d0 + cq * 2;
        *(float2*)(g_opart + (size_t)r0 * 8192 + pidx * 64 + cd)
            = make_float2(o[mf][0], o[mf][1]);
        *(float2*)(g_opart + (size_t)(r0 + 8) * 8192 + pidx * 64 + cd)
            = make_float2(o[mf][2], o[mf][3]);
    }
}

// ---------------- combine 4 partials/row + the 4 batch-local new KV positions ----------------
// warp per (h,m) row; grid 256 x 8 warps = 2048 rows.
__global__ void __launch_bounds__(256) attn_combine(const float* __restrict__ mask)
{
    const int tid = threadIdx.x;
    const int lane = tid & 31;
    const int rg = tid >> 5;
    const int R = blockIdx.x * 8 + rg;
    const int h = R >> 6, m = R & 63, b = m >> 2;

    float2 q2 = *(const float2*)(g_q + m * E_DIM + h * HD + lane * 2);
    float sn[4];
#pragma unroll
    for (int tp = 0; tp < 4; tp++) {
        float2 k2 = *(const float2*)(g_k + (b * 4 + tp) * E_DIM + h * HD + lane * 2);
        float pv = q2.x * k2.x + q2.y * k2.y;
#pragma unroll
        for (int off = 16; off > 0; off >>= 1)
            pv += __shfl_xor_sync(0xffffffffu, pv, off);
        sn[tp] = fmaxf(pv + mask[m * S_LEN + P_LEN + tp], NEG_MAX);
    }

    float pm[4], pl[4];
#pragma unroll
    for (int p = 0; p < 4; p++) {
        pm[p] = g_pm[m * 128 + h * 4 + p];
        pl[p] = g_pl[m * 128 + h * 4 + p];
    }

    float M = fmaxf(fmaxf(pm[0], pm[1]), fmaxf(pm[2], pm[3]));
#pragma unroll
    for (int tp = 0; tp < 4; tp++) M = fmaxf(M, sn[tp]);

    float ep[4], esn[4], L = 0.0f;
#pragma unroll
    for (int p = 0; p < 4; p++) { ep[p] = __expf(pm[p] - M); L += pl[p] * ep[p]; }
#pragma unroll
    for (int tp = 0; tp < 4; tp++) { esn[tp] = __expf(sn[tp] - M); L += esn[tp]; }

    float ox = 0.0f, oy = 0.0f;
#pragma unroll
    for (int p = 0; p < 4; p++) {
        float2 pt = *(const float2*)(g_opart + (size_t)m * 8192 + (h * 4 + p) * 64 + lane * 2);
        ox += pt.x * ep[p]; oy += pt.y * ep[p];
    }
#pragma unroll
    for (int tp = 0; tp < 4; tp++) {
        float2 v2 = *(const float2*)(g_v + (b * 4 + tp) * E_DIM + h * HD + lane * 2);
        ox += esn[tp] * v2.x; oy += esn[tp] * v2.y;
    }
    float inv = 1.0f / L;
    *(float2*)(g_attn + m * E_DIM + h * HD + lane * 2) = make_float2(ox * inv, oy * inv);
}

// ---------------- launch ----------------
extern "C" void kernel_launch(void* const* d_in, const int* in_sizes, int n_in,
                              void* d_out, int out_size)
{
    const float* hs   = (const float*)d_in[0];
    const float* pk   = (const float*)d_in[1];
    const float* pv   = (const float*)d_in[2];
    const float* mask = (const float*)d_in[3];
    const float* Wq   = (const float*)d_in[4];
    const float* bq   = (const float*)d_in[5];
    const float* Wk   = (const float*)d_in[6];
    const float* bk   = (const float*)d_in[7];
    const float* Wv   = (const float*)d_in[8];
    const float* bv   = (const float*)d_in[9];
    const float* Wo   = (const float*)d_in[10];
    const float* bo   = (const float*)d_in[11];
    float* out = (float*)d_out;

    const int gemm_smem = 4 * 128 * 36 * 4;   // 73728
    const int attn_smem = (64 * 68 + 2 * 128 * 68 + 2 * 128 * 72 + 64 * 132 + 192) * 4; // 195328

    cudaFuncSetAttribute(gemm_w, cudaFuncAttributeMaxDynamicSharedMemorySize, gemm_smem);
    cudaFuncSetAttribute(attn_part, cudaFuncAttributeMaxDynamicSharedMemorySize, attn_smem);

    // QKV projections: split-K 4, 384 blocks
    gemm_w<<<dim3(32, 3, 4), 256, gemm_smem>>>(hs, Wq, Wk, Wv, 512);
    reduce_qkv<<<384, 256>>>(bq, bk, bv);
    // attention over past cache (online-softmax flash decoding)
    attn_part<<<128, 256, attn_smem>>>(pk, pv, mask);
    // merge 4 partials + new-token KV
    attn_combine<<<256, 256>>>(mask);
    // output projection: split-K 8, 256 blocks (A=nullptr -> g_attn device-side)
    gemm_w<<<dim3(32, 1, 8), 256, gemm_smem>>>(nullptr, Wo, Wo, Wo, 256);
    reduce_o<<<128, 256>>>(bo, out);
}

// round 9
// speedup vs baseline: 1.2154x; 1.2154x over previous
#include <cuda_runtime.h>
#include <cstdint>

#define E_DIM 2048
#define H_NUM 32
#define HD 64
#define P_LEN 4096
#define S_LEN 4100
#define M_ROWS 64
#define NPART 8
#define NEG_MAX (-3.4028234663852886e38f)

// ---------------- scratch (device globals: no allocs allowed) ----------------
__device__ __align__(256) float g_q[M_ROWS * E_DIM];      // tf32-rounded, pre-scaled Q
__device__ __align__(256) float g_k[M_ROWS * E_DIM];
__device__ __align__(256) float g_v[M_ROWS * E_DIM];
__device__ __align__(256) float g_attn[M_ROWS * E_DIM];
// opart: [m][h][p][d]  (m*16384 + h*512 + p*64 + d)
__device__ __align__(256) float g_opart[M_ROWS * H_NUM * NPART * HD];
// pm/pl: [m][h][p]     (m*256 + h*8 + p)
__device__ __align__(256) float g_pm[M_ROWS * H_NUM * NPART];
__device__ __align__(256) float g_pl[M_ROWS * H_NUM * NPART];
__device__ __align__(256) float g_pp[12 * M_ROWS * E_DIM];   // split-K partials

// ---------------- helpers ----------------
__device__ __forceinline__ uint32_t f2tf(float f) {
    uint32_t u;
    asm("cvt.rna.tf32.f32 %0, %1;" : "=r"(u) : "f"(f));
    return u;
}

__device__ __forceinline__ void mma_tf32(float* c, const uint32_t* a, uint32_t b0, uint32_t b1) {
    asm volatile(
        "mma.sync.aligned.m16n8k8.row.col.f32.tf32.tf32.f32 "
        "{%0,%1,%2,%3},{%4,%5,%6,%7},{%8,%9},{%0,%1,%2,%3};"
        : "+f"(c[0]), "+f"(c[1]), "+f"(c[2]), "+f"(c[3])
        : "r"(a[0]), "r"(a[1]), "r"(a[2]), "r"(a[3]), "r"(b0), "r"(b1));
}

__device__ __forceinline__ void cp16(float* smem_dst, const float* gsrc) {
    uint32_t s = (uint32_t)__cvta_generic_to_shared(smem_dst);
    asm volatile("cp.async.cg.shared.global [%0], [%1], 16;" :: "r"(s), "l"(gsrc));
}
__device__ __forceinline__ void cp_commit() {
    asm volatile("cp.async.commit_group;");
}
template<int N> __device__ __forceinline__ void cp_wait() {
    asm volatile("cp.async.wait_group %0;" :: "n"(N));
}

// ---------------- W-major split-K projection GEMM ----------------
// C[f, t] = sum_k W[f,k] * A[t,k]; grid (32, n_mats, ksplit); A==nullptr -> g_attn.
__global__ void __launch_bounds__(256) gemm_w(
    const float* __restrict__ A,
    const float* __restrict__ W0, const float* __restrict__ W1, const float* __restrict__ W2,
    int kspan)
{
    extern __shared__ float sm[];
    const int STAGE = 128 * 36;

    if (A == nullptr) A = g_attn;
    const float* W = (blockIdx.y == 0) ? W0 : (blockIdx.y == 1) ? W1 : W2;
    const int fbase = blockIdx.x * 64;
    const int k0 = blockIdx.z * kspan;
    float* part = g_pp + (size_t)(blockIdx.z * gridDim.y + blockIdx.y) * (M_ROWS * E_DIM);

    const int tid = threadIdx.x;
    const int lane = tid & 31, wid = tid >> 5;
    const int rb = lane >> 2, cq = lane & 3;
    const int m0 = (wid >> 1) * 16;
    const int n0 = (wid & 1) * 32;

    float c[4][4];
#pragma unroll
    for (int i = 0; i < 4; i++)
#pragma unroll
        for (int j = 0; j < 4; j++) c[i][j] = 0.0f;

    auto load_stage = [&](int buf, int kk0) {
        float* ws = sm + buf * STAGE;
        float* as = ws + 64 * 36;
        int row = tid >> 3, kc = tid & 7;
        cp16(ws + row * 36 + kc * 4,        W + (size_t)(fbase + row) * E_DIM + kk0 + kc * 4);
        cp16(ws + (row + 32) * 36 + kc * 4, W + (size_t)(fbase + row + 32) * E_DIM + kk0 + kc * 4);
        cp16(as + row * 36 + kc * 4,        A + (row) * E_DIM + kk0 + kc * 4);
        cp16(as + (row + 32) * 36 + kc * 4, A + (row + 32) * E_DIM + kk0 + kc * 4);
    };

#pragma unroll
    for (int s = 0; s < 3; s++) { load_stage(s, k0 + s * 32); cp_commit(); }

    const int NITER = kspan / 32;
    for (int it = 0; it < NITER; it++) {
        cp_wait<2>();
        __syncthreads();
        float* ws = sm + (it & 3) * STAGE;
        float* as = ws + 64 * 36;
#pragma unroll
        for (int ks = 0; ks < 4; ks++) {
            int kk = ks * 8 + cq;
            uint32_t a[4];
            a[0] = f2tf(ws[(m0 + rb) * 36 + kk]);
            a[1] = f2tf(ws[(m0 + 8 + rb) * 36 + kk]);
            a[2] = f2tf(ws[(m0 + rb) * 36 + kk + 4]);
            a[3] = f2tf(ws[(m0 + 8 + rb) * 36 + kk + 4]);
#pragma unroll
            for (int nf = 0; nf < 4; nf++) {
                int nn = n0 + nf * 8 + rb;
                uint32_t b0 = f2tf(as[nn * 36 + kk]);
                uint32_t b1 = f2tf(as[nn * 36 + kk + 4]);
                mma_tf32(c[nf], a, b0, b1);
            }
        }
        int nx = it + 3;
        if (nx < NITER) load_stage(nx & 3, k0 + nx * 32);
        cp_commit();
    }

    const int f = fbase + m0 + rb;
#pragma unroll
    for (int nf = 0; nf < 4; nf++) {
        int t0 = n0 + nf * 8 + cq * 2;
        part[t0 * E_DIM + f]           = c[nf][0];
        part[(t0 + 1) * E_DIM + f]     = c[nf][1];
        part[t0 * E_DIM + f + 8]       = c[nf][2];
        part[(t0 + 1) * E_DIM + f + 8] = c[nf][3];
    }
}

// ---------------- reduce split-K partials ----------------
// QKV: slots {mat, mat+3, mat+6, mat+9}; Q gets scale 0.125 AND tf32 pre-rounding.
__global__ void __launch_bounds__(256) reduce_qkv(
    const float* __restrict__ bq, const float* __restrict__ bk, const float* __restrict__ bv)
{
    int gid = blockIdx.x * 256 + threadIdx.x;    // 0..98303
    int mat = gid >> 15;
    int r = gid & 32767;
    int f4 = r & 511;
    const float4* pp = (const float4*)g_pp;
    float4 a = pp[(size_t)mat * 32768 + r];
    float4 b = pp[(size_t)(mat + 3) * 32768 + r];
    float4 c = pp[(size_t)(mat + 6) * 32768 + r];
    float4 d = pp[(size_t)(mat + 9) * 32768 + r];
    const float* bias = (mat == 0) ? bq : (mat == 1) ? bk : bv;
    float4 bb = ((const float4*)bias)[f4];
    float4 o;
    o.x = a.x + b.x + c.x + d.x + bb.x;
    o.y = a.y + b.y + c.y + d.y + bb.y;
    o.z = a.z + b.z + c.z + d.z + bb.z;
    o.w = a.w + b.w + c.w + d.w + bb.w;
    if (mat == 0) {
        o.x = __uint_as_float(f2tf(o.x * 0.125f));
        o.y = __uint_as_float(f2tf(o.y * 0.125f));
        o.z = __uint_as_float(f2tf(o.z * 0.125f));
        o.w = __uint_as_float(f2tf(o.w * 0.125f));
    }
    float* out = (mat == 0) ? g_q : (mat == 1) ? g_k : g_v;
    ((float4*)out)[r] = o;
}

// O-proj: slots 0..7, add bias, write d_out. grid 128x256
__global__ void __launch_bounds__(256) reduce_o(const float* __restrict__ bo, float* __restrict__ out)
{
    int r = blockIdx.x * 256 + threadIdx.x;      // 0..32767
    int f4 = r & 511;
    const float4* pp = (const float4*)g_pp;
    float4 bb = ((const float4*)bo)[f4];
    float ox = bb.x, oy = bb.y, oz = bb.z, ow = bb.w;
#pragma unroll
    for (int s = 0; s < 8; s++) {
        float4 a = pp[(size_t)s * 32768 + r];
        ox += a.x; oy += a.y; oz += a.z; ow += a.w;
    }
    ((float4*)out)[r] = make_float4(ox, oy, oz, ow);
}

// ---------------- attention: register-resident online-softmax flash decoding ----------------
// Grid 256 = (head h = bid>>3, part p = bid&7). Block = 128 threads = 4 warps.
// Warp w owns rows w*16..w*16+15 x ALL 64 cols of each 64-position chunk; 8 chunks/block.
// Scores, probs, running (M,L), O accumulator all in registers. KV triple-buffered,
// ONE barrier per chunk. Probs C-frag reused directly as GEMM-O A-frag via V row permute.
#define KST 68
#define VST 76
__global__ void __launch_bounds__(128, 2) attn_part(
    const float* __restrict__ kpast, const float* __restrict__ vpast,
    const float* __restrict__ mask)
{
    extern __shared__ float sm[];
    float* ks = sm;                    // 3 x [64][68]
    float* vs = sm + 3 * 64 * KST;     // 3 x [64][76]

    const int tid = threadIdx.x;
    const int lane = tid & 31, wid = tid >> 5;
    const int rb = lane >> 2, cq = lane & 3;
    const int h = blockIdx.x >> 3;
    const int p = blockIdx.x & 7;
    const int r0 = wid * 16 + rb;      // rows r0, r0+8

    // Q fragments (registers for whole block; g_q is pre-rounded tf32)
    uint32_t qa[8][4];
    {
        const float* q0 = g_q + (size_t)r0 * E_DIM + h * HD;
        const float* q1 = q0 + 8 * E_DIM;
#pragma unroll
        for (int kst = 0; kst < 8; kst++) {
            qa[kst][0] = __float_as_uint(q0[kst * 8 + cq]);
            qa[kst][1] = __float_as_uint(q1[kst * 8 + cq]);
            qa[kst][2] = __float_as_uint(q0[kst * 8 + cq + 4]);
            qa[kst][3] = __float_as_uint(q1[kst * 8 + cq + 4]);
        }
    }

    auto prefetch = [&](int ci, int slot) {
        int s0 = (p * 8 + ci) * 64;
        float* kb = ks + slot * (64 * KST);
        float* vb = vs + slot * (64 * VST);
#pragma unroll
        for (int i = 0; i < 8; i++) {
            int cc = tid + i * 128;
            int s = cc >> 4, kc = cc & 15;
            cp16(kb + s * KST + kc * 4, kpast + ((size_t)h * P_LEN + s0 + s) * HD + kc * 4);
        }
#pragma unroll
        for (int i = 0; i < 8; i++) {
            int cc = tid + i * 128;
            int s = cc >> 4, kc = cc & 15;
            cp16(vb + s * VST + kc * 4, vpast + ((size_t)h * P_LEN + s0 + s) * HD + kc * 4);
        }
        cp_commit();
    };

    prefetch(0, 0);
    prefetch(1, 1);

    float M0 = NEG_MAX, M1 = NEG_MAX, L0 = 0.0f, L1 = 0.0f;
    float o[8][4];
#pragma unroll
    for (int i = 0; i < 8; i++)
#pragma unroll
        for (int j = 0; j < 4; j++) o[i][j] = 0.0f;

    for (int ci = 0; ci < 8; ci++) {
        if (ci < 6) cp_wait<1>(); else cp_wait<0>();
        __syncthreads();                         // data visible; all warps past chunk ci-1
        if (ci + 2 < 8) prefetch(ci + 2, (ci + 2) % 3);  // safe: slot (ci+2)%3 == (ci-1)%3, done

        const int slot = ci % 3;
        const float* kb = ks + slot * (64 * KST);
        const float* vb = vs + slot * (64 * VST);
        const int s0 = (p * 8 + ci) * 64;

        // mask values (row r0, r0+8) x 8 col-pairs
        float2 mkA[8], mkB[8];
        {
            const float* mrow0 = mask + (size_t)r0 * S_LEN + s0 + 2 * cq;
            const float* mrow1 = mrow0 + 8 * S_LEN;
#pragma unroll
            for (int nf = 0; nf < 8; nf++) {
                mkA[nf] = *(const float2*)(mrow0 + nf * 8);
                mkB[nf] = *(const float2*)(mrow1 + nf * 8);
            }
        }

        // GEMM-S: c[nf] = Q(16 rows) @ K(cols nf*8..)^T
        float c[8][4];
#pragma unroll
        for (int i = 0; i < 8; i++)
#pragma unroll
            for (int j = 0; j < 4; j++) c[i][j] = 0.0f;
#pragma unroll
        for (int kst = 0; kst < 8; kst++) {
            int kk = kst * 8 + cq;
#pragma unroll
            for (int nf = 0; nf < 8; nf++) {
                const float* kr = kb + (nf * 8 + rb) * KST;
                uint32_t b0 = f2tf(kr[kk]);
                uint32_t b1 = f2tf(kr[kk + 4]);
                mma_tf32(c[nf], qa[kst], b0, b1);
            }
        }

        // mask + clamp, then register online softmax (row lives in 4 lanes: 2 shuffles)
        float mx0 = NEG_MAX, mx1 = NEG_MAX;
#pragma unroll
        for (int nf = 0; nf < 8; nf++) {
            c[nf][0] = fmaxf(c[nf][0] + mkA[nf].x, NEG_MAX);
            c[nf][1] = fmaxf(c[nf][1] + mkA[nf].y, NEG_MAX);
            c[nf][2] = fmaxf(c[nf][2] + mkB[nf].x, NEG_MAX);
            c[nf][3] = fmaxf(c[nf][3] + mkB[nf].y, NEG_MAX);
            mx0 = fmaxf(mx0, fmaxf(c[nf][0], c[nf][1]));
            mx1 = fmaxf(mx1, fmaxf(c[nf][2], c[nf][3]));
        }
        mx0 = fmaxf(mx0, __shfl_xor_sync(0xffffffffu, mx0, 1));
        mx0 = fmaxf(mx0, __shfl_xor_sync(0xffffffffu, mx0, 2));
        mx1 = fmaxf(mx1, __shfl_xor_sync(0xffffffffu, mx1, 1));
        mx1 = fmaxf(mx1, __shfl_xor_sync(0xffffffffu, mx1, 2));

        float M0n = fmaxf(M0, mx0), M1n = fmaxf(M1, mx1);
        float f0 = __expf(M0 - M0n), f1 = __expf(M1 - M1n);

        uint32_t pa[8][4];
        float s0a = 0.0f, s1a = 0.0f;
#pragma unroll
        for (int nf = 0; nf < 8; nf++) {
            float p0 = __expf(c[nf][0] - M0n); s0a += p0; pa[nf][0] = f2tf(p0);
            float p1 = __expf(c[nf][1] - M0n); s0a += p1; pa[nf][1] = f2tf(p1);
            float p2 = __expf(c[nf][2] - M1n); s1a += p2; pa[nf][2] = f2tf(p2);
            float p3 = __expf(c[nf][3] - M1n); s1a += p3; pa[nf][3] = f2tf(p3);
        }
        s0a += __shfl_xor_sync(0xffffffffu, s0a, 1);
        s0a += __shfl_xor_sync(0xffffffffu, s0a, 2);
        s1a += __shfl_xor_sync(0xffffffffu, s1a, 1);
        s1a += __shfl_xor_sync(0xffffffffu, s1a, 2);
        L0 = L0 * f0 + s0a;  M0 = M0n;
        L1 = L1 * f1 + s1a;  M1 = M1n;

        // rescale O, then GEMM-O with probs C-frags as A-frags (V rows permuted)
#pragma unroll
        for (int df = 0; df < 8; df++) {
            o[df][0] *= f0; o[df][1] *= f0;
            o[df][2] *= f1; o[df][3] *= f1;
        }
#pragma unroll
        for (int kst = 0; kst < 8; kst++) {
            uint32_t aP[4] = { pa[kst][0], pa[kst][2], pa[kst][1], pa[kst][3] };
            const float* v0 = vb + (kst * 8 + 2 * cq) * VST + rb;
            const float* v1 = v0 + VST;
#pragma unroll
            for (int df = 0; df < 8; df++) {
                uint32_t b0 = f2tf(v0[df * 8]);
                uint32_t b1 = f2tf(v1[df * 8]);
                mma_tf32(o[df], aP, b0, b1);
            }
        }
    }

    // store partial O + (M, L)
    {
        float* o0 = g_opart + (size_t)r0 * (H_NUM * NPART * HD) + h * (NPART * HD) + p * HD + 2 * cq;
        float* o1 = o0 + 8 * (H_NUM * NPART * HD);
#pragma unroll
        for (int df = 0; df < 8; df++) {
            *(float2*)(o0 + df * 8) = make_float2(o[df][0], o[df][1]);
            *(float2*)(o1 + df * 8) = make_float2(o[df][2], o[df][3]);
        }
        if (cq == 0) {
            g_pm[r0 * (H_NUM * NPART) + h * NPART + p] = M0;
            g_pl[r0 * (H_NUM * NPART) + h * NPART + p] = L0;
            g_pm[(r0 + 8) * (H_NUM * NPART) + h * NPART + p] = M1;
            g_pl[(r0 + 8) * (H_NUM * NPART) + h * NPART + p] = L1;
        }
    }
}

// ---------------- combine 8 partials/row + the 4 batch-local new KV positions ----------------
// warp per (h,m) row; grid 256 x 8 warps = 2048 rows.
__global__ void __launch_bounds__(256) attn_combine(const float* __restrict__ mask)
{
    const int tid = threadIdx.x;
    const int lane = tid & 31;
    const int rg = tid >> 5;
    const int R = blockIdx.x * 8 + rg;
    const int h = R >> 6, m = R & 63, b = m >> 2;

    float2 q2 = *(const float2*)(g_q + m * E_DIM + h * HD + lane * 2);
    float sn[4];
#pragma unroll
    for (int tp = 0; tp < 4; tp++) {
        float2 k2 = *(const float2*)(g_k + (b * 4 + tp) * E_DIM + h * HD + lane * 2);
        float pv = q2.x * k2.x + q2.y * k2.y;
#pragma unroll
        for (int off = 16; off > 0; off >>= 1)
            pv += __shfl_xor_sync(0xffffffffu, pv, off);
        sn[tp] = fmaxf(pv + mask[m * S_LEN + P_LEN + tp], NEG_MAX);
    }

    // each lane holds one of 8 parts (replicated x4 across the warp)
    float pmv = g_pm[m * (H_NUM * NPART) + h * NPART + (lane & 7)];
    float plv = g_pl[m * (H_NUM * NPART) + h * NPART + (lane & 7)];

    float M = pmv;
    M = fmaxf(M, __shfl_xor_sync(0xffffffffu, M, 1));
    M = fmaxf(M, __shfl_xor_sync(0xffffffffu, M, 2));
    M = fmaxf(M, __shfl_xor_sync(0xffffffffu, M, 4));
#pragma unroll
    for (int tp = 0; tp < 4; tp++) M = fmaxf(M, sn[tp]);

    float epv = __expf(pmv - M);
    float L = plv * epv;
    L += __shfl_xor_sync(0xffffffffu, L, 1);
    L += __shfl_xor_sync(0xffffffffu, L, 2);
    L += __shfl_xor_sync(0xffffffffu, L, 4);
    float esn[4];
#pragma unroll
    for (int tp = 0; tp < 4; tp++) { esn[tp] = __expf(sn[tp] - M); L += esn[tp]; }

    const float* opr = g_opart + (size_t)m * (H_NUM * NPART * HD) + h * (NPART * HD) + lane * 2;
    float ox = 0.0f, oy = 0.0f;
#pragma unroll
    for (int pp = 0; pp < 8; pp++) {
        float w = __shfl_sync(0xffffffffu, epv, pp, 8);
        float2 pt = *(const float2*)(opr + pp * HD);
        ox += pt.x * w; oy += pt.y * w;
    }
#pragma unroll
    for (int tp = 0; tp < 4; tp++) {
        float2 v2 = *(const float2*)(g_v + (b * 4 + tp) * E_DIM + h * HD + lane * 2);
        ox += esn[tp] * v2.x; oy += esn[tp] * v2.y;
    }
    float inv = 1.0f / L;
    *(float2*)(g_attn + m * E_DIM + h * HD + lane * 2) = make_float2(ox * inv, oy * inv);
}

// ---------------- launch ----------------
extern "C" void kernel_launch(void* const* d_in, const int* in_sizes, int n_in,
                              void* d_out, int out_size)
{
    const float* hs   = (const float*)d_in[0];
    const float* pk   = (const float*)d_in[1];
    const float* pv   = (const float*)d_in[2];
    const float* mask = (const float*)d_in[3];
    const float* Wq   = (const float*)d_in[4];
    const float* bq   = (const float*)d_in[5];
    const float* Wk   = (const float*)d_in[6];
    const float* bk   = (const float*)d_in[7];
    const float* Wv   = (const float*)d_in[8];
    const float* bv   = (const float*)d_in[9];
    const float* Wo   = (const float*)d_in[10];
    const float* bo   = (const float*)d_in[11];
    float* out = (float*)d_out;

    const int gemm_smem = 4 * 128 * 36 * 4;                  // 73728
    const int attn_smem = 3 * (64 * KST + 64 * VST) * 4;     // 110592

    cudaFuncSetAttribute(gemm_w, cudaFuncAttributeMaxDynamicSharedMemorySize, gemm_smem);
    cudaFuncSetAttribute(attn_part, cudaFuncAttributeMaxDynamicSharedMemorySize, attn_smem);

    // QKV projections: split-K 4, 384 blocks
    gemm_w<<<dim3(32, 3, 4), 256, gemm_smem>>>(hs, Wq, Wk, Wv, 512);
    reduce_qkv<<<384, 256>>>(bq, bk, bv);
    // attention over past cache (register-resident flash decoding)
    attn_part<<<256, 128, attn_smem>>>(pk, pv, mask);
    // merge 8 partials + new-token KV
    attn_combine<<<256, 256>>>(mask);
    // output projection: split-K 8, 256 blocks (A=nullptr -> g_attn device-side)
    gemm_w<<<dim3(32, 1, 8), 256, gemm_smem>>>(nullptr, Wo, Wo, Wo, 256);
    reduce_o<<<128, 256>>>(bo, out);
}